// round 1
// baseline (speedup 1.0000x reference)
#include <cuda_runtime.h>
#include <math.h>

#define NXD 32
#define HID 256
#define NOUT 528
#define BM 64
#define NTHREADS 512
#define KC 16

// shared-memory layout (float offsets)
//  sH2 [0, 16384)            64x256  — GEMM2 output / GEMM3 input
//  sW  [16384, 20480)        16x256  — streamed weight tile
//  sQ  [20480, 21504)        32x32   — Q, persists whole kernel
//  sX  [21504, 23552)        64x32   — log-diag (dead after GEMM1)
//  sH1 [23552, 39936)        64x256  — GEMM1 out (dead after GEMM2)
//  sL  [21504, 55296)        64x528  — packed L, overlays sX+sH1 (live in GEMM3/LLT)
#define OFF_H2 0
#define OFF_W  16384
#define OFF_Q  20480
#define OFF_X  21504
#define OFF_H1 23552
#define OFF_L  21504
#define SMEM_FLOATS 55296   // 221184 bytes

__global__ void __launch_bounds__(NTHREADS, 1) covnet_kernel(
    const float* __restrict__ P_prev,
    const float* __restrict__ W1, const float* __restrict__ b1,
    const float* __restrict__ W2, const float* __restrict__ b2,
    const float* __restrict__ W3, const float* __restrict__ b3,
    const float* __restrict__ Q, float* __restrict__ out)
{
    extern __shared__ float sm[];
    float* sH2 = sm + OFF_H2;
    float* sW  = sm + OFF_W;
    float* sQ  = sm + OFF_Q;
    float* sX  = sm + OFF_X;
    float* sH1 = sm + OFF_H1;
    float* sL  = sm + OFF_L;

    const int tid = threadIdx.x;
    const int tx  = tid & 31;        // col lane
    const int sg  = tid >> 5;        // 0..15 sample group (== warp id)
    const int s0  = sg * 4;          // 4 samples per thread
    const size_t b0 = (size_t)blockIdx.x * BM;

    // Q -> smem (persists)
    for (int i = tid; i < NXD * NXD; i += NTHREADS) sQ[i] = Q[i];

    // gather diagonal, log(clip(.,1e-6))
    for (int i = tid; i < BM * NXD; i += NTHREADS) {
        int s = i >> 5, d = i & 31;
        float v = P_prev[(b0 + (size_t)s) * 1024 + d * 33];
        sX[s * NXD + d] = logf(fmaxf(v, 1e-6f));
    }
    __syncthreads();

    // ================= GEMM1: h1 = tanh(x @ W1 + b1), K=32 =================
    {
        float acc[4][8];
        #pragma unroll
        for (int j = 0; j < 8; j++) {
            float bv = __ldg(&b1[tx + 32 * j]);
            #pragma unroll
            for (int ss = 0; ss < 4; ss++) acc[ss][j] = bv;
        }
        for (int kc = 0; kc < NXD; kc += KC) {
            const float4* wsrc = (const float4*)(W1 + kc * HID);
            float4* wdst = (float4*)sW;
            for (int i = tid; i < KC * HID / 4; i += NTHREADS) wdst[i] = wsrc[i];
            __syncthreads();
            #pragma unroll
            for (int kk = 0; kk < KC; kk++) {
                float xv[4];
                #pragma unroll
                for (int ss = 0; ss < 4; ss++) xv[ss] = sX[(s0 + ss) * NXD + kc + kk];
                float wv[8];
                #pragma unroll
                for (int j = 0; j < 8; j++) wv[j] = sW[kk * HID + tx + 32 * j];
                #pragma unroll
                for (int ss = 0; ss < 4; ss++)
                    #pragma unroll
                    for (int j = 0; j < 8; j++) acc[ss][j] += xv[ss] * wv[j];
            }
            __syncthreads();
        }
        #pragma unroll
        for (int ss = 0; ss < 4; ss++)
            #pragma unroll
            for (int j = 0; j < 8; j++)
                sH1[(s0 + ss) * HID + tx + 32 * j] = tanhf(acc[ss][j]);
    }
    __syncthreads();

    // ================= GEMM2: h2 = tanh(h1 @ W2 + b2), K=256 ===============
    {
        float acc[4][8];
        #pragma unroll
        for (int j = 0; j < 8; j++) {
            float bv = __ldg(&b2[tx + 32 * j]);
            #pragma unroll
            for (int ss = 0; ss < 4; ss++) acc[ss][j] = bv;
        }
        for (int kc = 0; kc < HID; kc += KC) {
            const float4* wsrc = (const float4*)(W2 + kc * HID);
            float4* wdst = (float4*)sW;
            for (int i = tid; i < KC * HID / 4; i += NTHREADS) wdst[i] = wsrc[i];
            __syncthreads();
            #pragma unroll
            for (int kk = 0; kk < KC; kk++) {
                float hv[4];
                #pragma unroll
                for (int ss = 0; ss < 4; ss++) hv[ss] = sH1[(s0 + ss) * HID + kc + kk];
                float wv[8];
                #pragma unroll
                for (int j = 0; j < 8; j++) wv[j] = sW[kk * HID + tx + 32 * j];
                #pragma unroll
                for (int ss = 0; ss < 4; ss++)
                    #pragma unroll
                    for (int j = 0; j < 8; j++) acc[ss][j] += hv[ss] * wv[j];
            }
            __syncthreads();
        }
        #pragma unroll
        for (int ss = 0; ss < 4; ss++)
            #pragma unroll
            for (int j = 0; j < 8; j++)
                sH2[(s0 + ss) * HID + tx + 32 * j] = tanhf(acc[ss][j]);
    }
    __syncthreads();

    // ====== GEMM3: out = h2 @ W3 + b3 (N=528 in 4x128 + 16), transform -> sL
    for (int chunk = 0; chunk < 5; chunk++) {
        const int n0 = chunk * 128;
        const int ncols = (chunk < 4) ? 128 : (NOUT - 512);  // 16 tail
        float acc[4][4];
        #pragma unroll
        for (int j = 0; j < 4; j++) {
            int cc = tx + 32 * j;
            float bv = (cc < ncols) ? __ldg(&b3[n0 + cc]) : 0.f;
            #pragma unroll
            for (int ss = 0; ss < 4; ss++) acc[ss][j] = bv;
        }
        for (int kc = 0; kc < HID; kc += KC) {
            for (int i = tid; i < KC * 128; i += NTHREADS) {
                int kk = i >> 7, cc = i & 127;
                sW[i] = (cc < ncols) ? W3[(kc + kk) * NOUT + n0 + cc] : 0.f;
            }
            __syncthreads();
            #pragma unroll
            for (int kk = 0; kk < KC; kk++) {
                float hv[4];
                #pragma unroll
                for (int ss = 0; ss < 4; ss++) hv[ss] = sH2[(s0 + ss) * HID + kc + kk];
                float wv[4];
                #pragma unroll
                for (int j = 0; j < 4; j++) wv[j] = sW[kk * 128 + tx + 32 * j];
                #pragma unroll
                for (int ss = 0; ss < 4; ss++)
                    #pragma unroll
                    for (int j = 0; j < 4; j++) acc[ss][j] += hv[ss] * wv[j];
            }
            __syncthreads();
        }
        // activation transforms -> packed L
        #pragma unroll
        for (int j = 0; j < 4; j++) {
            int cc = tx + 32 * j;
            if (cc < ncols) {
                int c = n0 + cc;
                #pragma unroll
                for (int ss = 0; ss < 4; ss++) {
                    float v = acc[ss][j];
                    float lv;
                    if (c < NXD) {
                        float sp = (v > 20.f) ? v : log1pf(expf(v));
                        lv = fminf(fmaxf(sp + 0.01f, 0.01f), 100.f);
                    } else {
                        lv = 0.1f * tanhf(v);
                    }
                    sL[(s0 + ss) * NOUT + c] = lv;
                }
            }
        }
    }
    __syncthreads();

    // ================= P = L * L^T + Q =================
    // warp = 4 samples; lane k owns output column k; L[k][*] in registers.
    {
        const int k = tx;
        const int kbase = 32 + (k * (k - 1)) / 2;
        for (int ss = 0; ss < 4; ss++) {
            const int s = s0 + ss;
            const float* Lr = sL + s * NOUT;
            float Lk[32];
            #pragma unroll
            for (int j = 0; j < 32; j++) {
                float v = 0.f;
                if (j < k)       v = Lr[kbase + j];
                else if (j == k) v = Lr[k];
                Lk[j] = v;
            }
            float* Po = out + (b0 + (size_t)s) * 1024;
            #pragma unroll
            for (int i = 0; i < 32; i++) {
                float a = sQ[i * 32 + k];
                const int ib = 32 + (i * (i - 1)) / 2;
                #pragma unroll
                for (int j = 0; j < i; j++) {
                    float lij = Lr[ib + j];      // broadcast across warp
                    if (j <= k) a += lij * Lk[j];
                }
                float lii = Lr[i];               // diagonal term (j == i)
                if (i <= k) a += lii * Lk[i];
                Po[i * 32 + k] = a;
            }
        }
    }
}

extern "C" void kernel_launch(void* const* d_in, const int* in_sizes, int n_in,
                              void* d_out, int out_size) {
    const float* P_prev = (const float*)d_in[0];
    const float* W1 = (const float*)d_in[1];
    const float* b1 = (const float*)d_in[2];
    const float* W2 = (const float*)d_in[3];
    const float* b2 = (const float*)d_in[4];
    const float* W3 = (const float*)d_in[5];
    const float* b3 = (const float*)d_in[6];
    const float* Q  = (const float*)d_in[7];
    float* out = (float*)d_out;

    const int B = in_sizes[0] / (NXD * NXD);   // 65536
    const int grid = B / BM;                   // 1024

    static_assert(SMEM_FLOATS * 4 == 221184, "smem layout");
    cudaFuncSetAttribute(covnet_kernel,
                         cudaFuncAttributeMaxDynamicSharedMemorySize,
                         SMEM_FLOATS * sizeof(float));

    covnet_kernel<<<grid, NTHREADS, SMEM_FLOATS * sizeof(float)>>>(
        P_prev, W1, b1, W2, b2, W3, b3, Q, out);
}

// round 2
// speedup vs baseline: 2.1706x; 2.1706x over previous
#include <cuda_runtime.h>
#include <math.h>

#define NXD 32
#define HID 256
#define NOUT 528
#define BM 64
#define NTHREADS 512
#define KC 16

// shared-memory layout (float offsets)
//  sH2 [0, 16384)            64x256  — GEMM2 output / GEMM3 input
//  sW  [16384, 20480)        16x256  — streamed weight tile (also 256x16 tail)
//  sQ  [20480, 21504)        32x32   — Q, persists whole kernel
//  sX  [21504, 23552)        64x32   — log-diag (dead after GEMM1)
//  sH1 [23552, 39936)        64x256  — GEMM1 out (dead after GEMM2)
//  sL  [21504, 55296)        64x528  — packed L, overlays sX+sH1
#define OFF_H2 0
#define OFF_W  16384
#define OFF_Q  20480
#define OFF_X  21504
#define OFF_H1 23552
#define OFF_L  21504
#define SMEM_FLOATS 55296   // 221184 bytes

typedef unsigned long long u64;

__device__ __forceinline__ u64 pk2(float lo, float hi) {
    u64 d; asm("mov.b64 %0, {%1, %2};" : "=l"(d) : "f"(lo), "f"(hi)); return d;
}
__device__ __forceinline__ void fma2(u64& d, u64 a, u64 b) {
    asm("fma.rn.f32x2 %0, %1, %2, %0;" : "+l"(d) : "l"(a), "l"(b));
}
__device__ __forceinline__ float2 up2(u64 d) {
    float2 r; asm("mov.b64 {%0, %1}, %2;" : "=f"(r.x), "=f"(r.y) : "l"(d)); return r;
}

__device__ __forceinline__ float ftanh(float x) {
    x = fminf(fmaxf(x, -15.f), 15.f);
    float e = __expf(2.f * x);
    return __fdividef(e - 1.f, e + 1.f);
}
__device__ __forceinline__ float fsplus(float v) {
    float sp = (v > 20.f) ? v : __logf(1.f + __expf(v));
    return fminf(fmaxf(sp + 0.01f, 0.01f), 100.f);
}

__global__ void __launch_bounds__(NTHREADS, 1) covnet_kernel(
    const float* __restrict__ P_prev,
    const float* __restrict__ W1, const float* __restrict__ b1,
    const float* __restrict__ W2, const float* __restrict__ b2,
    const float* __restrict__ W3, const float* __restrict__ b3,
    const float* __restrict__ Q, float* __restrict__ out)
{
    extern __shared__ float sm[];
    float* sH2 = sm + OFF_H2;
    float* sW  = sm + OFF_W;
    float* sQ  = sm + OFF_Q;
    float* sX  = sm + OFF_X;
    float* sH1 = sm + OFF_H1;
    float* sL  = sm + OFF_L;

    const int tid = threadIdx.x;
    const int tx  = tid & 31;        // col lane
    const int sg  = tid >> 5;        // warp id = sample group
    const int s0  = sg * 4;          // 4 samples per warp
    const size_t b0 = (size_t)blockIdx.x * BM;

    // Q -> smem (persists)
    for (int i = tid; i < NXD * NXD; i += NTHREADS) sQ[i] = Q[i];

    // gather diagonal, log(clip(.,1e-6))
    for (int i = tid; i < BM * NXD; i += NTHREADS) {
        int s = i >> 5, d = i & 31;
        float v = P_prev[(b0 + (size_t)s) * 1024 + d * 33];
        sX[s * NXD + d] = __logf(fmaxf(v, 1e-6f));
    }
    __syncthreads();

    // ================= GEMM1: h1 = tanh(x @ W1 + b1), K=32 =================
    {
        u64 acc[4][4];
        #pragma unroll
        for (int jq = 0; jq < 2; jq++) {
            float4 b4 = *(const float4*)&b1[4 * tx + 128 * jq];
            u64 plo = pk2(b4.x, b4.y), phi = pk2(b4.z, b4.w);
            #pragma unroll
            for (int ss = 0; ss < 4; ss++) { acc[ss][2*jq] = plo; acc[ss][2*jq+1] = phi; }
        }
        for (int kc = 0; kc < NXD; kc += KC) {
            const float4* wsrc = (const float4*)(W1 + kc * HID);
            for (int i = tid; i < KC * HID / 4; i += NTHREADS) ((float4*)sW)[i] = wsrc[i];
            __syncthreads();
            #pragma unroll
            for (int k4 = 0; k4 < KC; k4 += 4) {
                float hva[4][4];
                #pragma unroll
                for (int ss = 0; ss < 4; ss++)
                    *(float4*)hva[ss] = *(const float4*)&sX[(s0 + ss) * NXD + kc + k4];
                #pragma unroll
                for (int u = 0; u < 4; u++) {
                    u64 hd[4];
                    #pragma unroll
                    for (int ss = 0; ss < 4; ss++) hd[ss] = pk2(hva[ss][u], hva[ss][u]);
                    #pragma unroll
                    for (int jq = 0; jq < 2; jq++) {
                        ulonglong2 w = *(const ulonglong2*)&sW[(k4 + u) * HID + 4 * tx + 128 * jq];
                        #pragma unroll
                        for (int ss = 0; ss < 4; ss++) {
                            fma2(acc[ss][2*jq],   hd[ss], w.x);
                            fma2(acc[ss][2*jq+1], hd[ss], w.y);
                        }
                    }
                }
            }
            __syncthreads();
        }
        #pragma unroll
        for (int ss = 0; ss < 4; ss++)
            #pragma unroll
            for (int jq = 0; jq < 2; jq++) {
                float2 p0 = up2(acc[ss][2*jq]), p1 = up2(acc[ss][2*jq+1]);
                float4 o = { ftanh(p0.x), ftanh(p0.y), ftanh(p1.x), ftanh(p1.y) };
                *(float4*)&sH1[(s0 + ss) * HID + 4 * tx + 128 * jq] = o;
            }
    }
    __syncthreads();

    // ================= GEMM2: h2 = tanh(h1 @ W2 + b2), K=256 ===============
    {
        u64 acc[4][4];
        #pragma unroll
        for (int jq = 0; jq < 2; jq++) {
            float4 b4 = *(const float4*)&b2[4 * tx + 128 * jq];
            u64 plo = pk2(b4.x, b4.y), phi = pk2(b4.z, b4.w);
            #pragma unroll
            for (int ss = 0; ss < 4; ss++) { acc[ss][2*jq] = plo; acc[ss][2*jq+1] = phi; }
        }
        for (int kc = 0; kc < HID; kc += KC) {
            const float4* wsrc = (const float4*)(W2 + kc * HID);
            for (int i = tid; i < KC * HID / 4; i += NTHREADS) ((float4*)sW)[i] = wsrc[i];
            __syncthreads();
            #pragma unroll
            for (int k4 = 0; k4 < KC; k4 += 4) {
                float hva[4][4];
                #pragma unroll
                for (int ss = 0; ss < 4; ss++)
                    *(float4*)hva[ss] = *(const float4*)&sH1[(s0 + ss) * HID + kc + k4];
                #pragma unroll
                for (int u = 0; u < 4; u++) {
                    u64 hd[4];
                    #pragma unroll
                    for (int ss = 0; ss < 4; ss++) hd[ss] = pk2(hva[ss][u], hva[ss][u]);
                    #pragma unroll
                    for (int jq = 0; jq < 2; jq++) {
                        ulonglong2 w = *(const ulonglong2*)&sW[(k4 + u) * HID + 4 * tx + 128 * jq];
                        #pragma unroll
                        for (int ss = 0; ss < 4; ss++) {
                            fma2(acc[ss][2*jq],   hd[ss], w.x);
                            fma2(acc[ss][2*jq+1], hd[ss], w.y);
                        }
                    }
                }
            }
            __syncthreads();
        }
        #pragma unroll
        for (int ss = 0; ss < 4; ss++)
            #pragma unroll
            for (int jq = 0; jq < 2; jq++) {
                float2 p0 = up2(acc[ss][2*jq]), p1 = up2(acc[ss][2*jq+1]);
                float4 o = { ftanh(p0.x), ftanh(p0.y), ftanh(p1.x), ftanh(p1.y) };
                *(float4*)&sH2[(s0 + ss) * HID + 4 * tx + 128 * jq] = o;
            }
    }
    __syncthreads();

    // ====== GEMM3 main: cols [0,512) in two 256-wide chunks ======
    for (int chunk = 0; chunk < 2; chunk++) {
        const int n0 = chunk * 256;
        u64 acc[4][4];
        #pragma unroll
        for (int jq = 0; jq < 2; jq++) {
            float4 b4 = *(const float4*)&b3[n0 + 4 * tx + 128 * jq];
            u64 plo = pk2(b4.x, b4.y), phi = pk2(b4.z, b4.w);
            #pragma unroll
            for (int ss = 0; ss < 4; ss++) { acc[ss][2*jq] = plo; acc[ss][2*jq+1] = phi; }
        }
        for (int kc = 0; kc < HID; kc += KC) {
            for (int i = tid; i < KC * 256 / 4; i += NTHREADS) {
                int r = i >> 6, c4 = i & 63;
                ((float4*)sW)[i] = *(const float4*)&W3[(kc + r) * NOUT + n0 + 4 * c4];
            }
            __syncthreads();
            #pragma unroll
            for (int k4 = 0; k4 < KC; k4 += 4) {
                float hva[4][4];
                #pragma unroll
                for (int ss = 0; ss < 4; ss++)
                    *(float4*)hva[ss] = *(const float4*)&sH2[(s0 + ss) * HID + kc + k4];
                #pragma unroll
                for (int u = 0; u < 4; u++) {
                    u64 hd[4];
                    #pragma unroll
                    for (int ss = 0; ss < 4; ss++) hd[ss] = pk2(hva[ss][u], hva[ss][u]);
                    #pragma unroll
                    for (int jq = 0; jq < 2; jq++) {
                        ulonglong2 w = *(const ulonglong2*)&sW[(k4 + u) * 256 + 4 * tx + 128 * jq];
                        #pragma unroll
                        for (int ss = 0; ss < 4; ss++) {
                            fma2(acc[ss][2*jq],   hd[ss], w.x);
                            fma2(acc[ss][2*jq+1], hd[ss], w.y);
                        }
                    }
                }
            }
            __syncthreads();
        }
        // activation transform -> packed L
        #pragma unroll
        for (int ss = 0; ss < 4; ss++)
            #pragma unroll
            for (int jq = 0; jq < 2; jq++) {
                int c = n0 + 4 * tx + 128 * jq;
                float2 p0 = up2(acc[ss][2*jq]), p1 = up2(acc[ss][2*jq+1]);
                float v[4] = { p0.x, p0.y, p1.x, p1.y };
                float o[4];
                #pragma unroll
                for (int q = 0; q < 4; q++)
                    o[q] = (c + q < NXD) ? fsplus(v[q]) : 0.1f * ftanh(v[q]);
                *(float4*)&sL[(s0 + ss) * NOUT + c] = *(float4*)o;
            }
    }

    // ====== GEMM3 tail: cols [512, 528) ======
    {
        // stage W3 tail [256 x 16] into sW
        for (int i = tid; i < 256 * 16; i += NTHREADS) {
            int k = i >> 4, c = i & 15;
            sW[i] = W3[k * NOUT + 512 + c];
        }
        __syncthreads();
        const int ss2 = tx >> 4;      // 0 or 1
        const int c   = tx & 15;
        const float bv = b3[512 + c];
        #pragma unroll
        for (int rep = 0; rep < 2; rep++) {
            int s = s0 + ss2 + 2 * rep;
            float a = bv;
            const float* hr = sH2 + s * HID;
            #pragma unroll 4
            for (int k = 0; k < HID; k++)
                a += hr[k] * sW[k * 16 + c];
            sL[s * NOUT + 512 + c] = 0.1f * ftanh(a);   // always lower-triangle cols
        }
    }
    __syncthreads();

    // ================= P = L * L^T + Q =================
    // warp = 4 samples; lane k owns output column k; L[k][*] in registers.
    {
        const int k = tx;
        const int kbase = 32 + (k * (k - 1)) / 2;
        for (int ss = 0; ss < 4; ss++) {
            const int s = s0 + ss;
            const float* Lr = sL + s * NOUT;
            float Lk[32];
            #pragma unroll
            for (int j = 0; j < 32; j++) {
                float v = 0.f;
                if (j < k)       v = Lr[kbase + j];
                else if (j == k) v = Lr[k];
                Lk[j] = v;
            }
            float* Po = out + (b0 + (size_t)s) * 1024;
            #pragma unroll
            for (int i = 0; i < 32; i++) {
                float a = sQ[i * 32 + k];
                const int ib = 32 + (i * (i - 1)) / 2;
                #pragma unroll
                for (int j = 0; j < i; j++) {
                    float lij = Lr[ib + j];      // broadcast across warp
                    if (j <= k) a += lij * Lk[j];
                }
                float lii = Lr[i];               // diagonal term (j == i)
                if (i <= k) a += lii * Lk[i];
                Po[i * 32 + k] = a;
            }
        }
    }
}

extern "C" void kernel_launch(void* const* d_in, const int* in_sizes, int n_in,
                              void* d_out, int out_size) {
    const float* P_prev = (const float*)d_in[0];
    const float* W1 = (const float*)d_in[1];
    const float* b1 = (const float*)d_in[2];
    const float* W2 = (const float*)d_in[3];
    const float* b2 = (const float*)d_in[4];
    const float* W3 = (const float*)d_in[5];
    const float* b3 = (const float*)d_in[6];
    const float* Q  = (const float*)d_in[7];
    float* out = (float*)d_out;

    const int B = in_sizes[0] / (NXD * NXD);   // 65536
    const int grid = B / BM;                   // 1024

    static_assert(SMEM_FLOATS * 4 == 221184, "smem layout");
    cudaFuncSetAttribute(covnet_kernel,
                         cudaFuncAttributeMaxDynamicSharedMemorySize,
                         SMEM_FLOATS * sizeof(float));

    covnet_kernel<<<grid, NTHREADS, SMEM_FLOATS * sizeof(float)>>>(
        P_prev, W1, b1, W2, b2, W3, b3, Q, out);
}

// round 3
// speedup vs baseline: 2.5565x; 1.1778x over previous
#include <cuda_runtime.h>
#include <math.h>

#define NXD 32
#define HID 256
#define NOUT 528
#define BM 64
#define NTHREADS 512
#define LSTRIDE 529

// shared layout (float offsets)
//  sH2t [0,16384)      256 x 64  transposed h2
//  sW0  [16384,18560)  8 x 272 ping
//  sW1  [18560,20736)  8 x 272 pong
//  sQ   [20736,21760)
//  sXt  [21760,23808)  32 x 64  (dead after GEMM1)
//  sH1t [23808,40192)  256 x 64 (dead after GEMM2)
//  sL   [21760,55616)  64 x 529 overlays sXt+sH1t
#define OFF_H2 0
#define OFF_W0 16384
#define OFF_W1 18560
#define OFF_Q  20736
#define OFF_X  21760
#define OFF_H1 23808
#define OFF_L  21760
#define SMEM_FLOATS 55616   // 222464 bytes

typedef unsigned long long u64;

__device__ __forceinline__ u64 pk2(float lo, float hi) {
    u64 d; asm("mov.b64 %0, {%1, %2};" : "=l"(d) : "f"(lo), "f"(hi)); return d;
}
__device__ __forceinline__ void fma2(u64& d, u64 a, u64 b) {
    asm("fma.rn.f32x2 %0, %1, %2, %0;" : "+l"(d) : "l"(a), "l"(b));
}
__device__ __forceinline__ float2 up2(u64 d) {
    float2 r; asm("mov.b64 {%0, %1}, %2;" : "=f"(r.x), "=f"(r.y) : "l"(d)); return r;
}
__device__ __forceinline__ float ftanh(float x) {
    x = fminf(fmaxf(x, -15.f), 15.f);
    float e = __expf(2.f * x);
    return __fdividef(e - 1.f, e + 1.f);
}
__device__ __forceinline__ float fsplus(float v) {
    float sp = (v > 20.f) ? v : __logf(1.f + __expf(v));
    return fminf(fmaxf(sp + 0.01f, 0.01f), 100.f);
}

// staging: one KCx(NCOLS) chunk, 8 rows. NCOLS=256 -> 1 float4/thread; 272 -> +tail
template<int NCOLS>
__device__ __forceinline__ void stage_ld(const float* __restrict__ Wg, int ldw,
                                         int ch, float4* rg) {
    const int NF4 = NCOLS * 2;            // float4s per chunk
    int idx = threadIdx.x;
    int kr = idx / (NCOLS / 4), c4 = idx - kr * (NCOLS / 4);
    rg[0] = *(const float4*)&Wg[(size_t)(ch * 8 + kr) * ldw + 4 * c4];
    if (NCOLS > 256) {
        int i2 = idx + 512;
        if (i2 < NF4) {
            int kr2 = i2 / (NCOLS / 4), c42 = i2 - kr2 * (NCOLS / 4);
            rg[1] = *(const float4*)&Wg[(size_t)(ch * 8 + kr2) * ldw + 4 * c42];
        }
    }
}
template<int NCOLS>
__device__ __forceinline__ void stage_st(float* buf, const float4* rg) {
    int idx = threadIdx.x;
    *(float4*)&buf[4 * idx] = rg[0];
    if (NCOLS > 256) {
        int i2 = idx + 512;
        if (i2 < NCOLS * 2) *(float4*)&buf[4 * i2] = rg[1];
    }
}

// Column-partitioned GEMM with sample-pair f32x2 accumulators.
// warp wp owns cols [16*wp, 16*wp+16) (+ single col 256+wp when NCOLS==272).
// lane tx owns samples 2*tx, 2*tx+1.
// MODE 0: out = tanh -> transposed store outp[c*64+s]
// MODE 1: GEMM3 cols [0,256): softplus/tanh -> sL[s*529+c]
// MODE 2: GEMM3 cols [256,528): tanh -> sL[s*529+256+c] (+ single col 512+wp)
template<int KTOT, int NCOLS, int MODE>
__device__ __forceinline__ void gemm_f2(
    float* sm, const float* __restrict__ Wg, int ldw,
    const float* __restrict__ bias,
    const float* sHin, float* outp, int tx, int wp)
{
    const int NCH = KTOT / 8;
    u64 acc[2][8];
    float accS[2] = {0.f, 0.f};
    {
        const float4 bA = *(const float4*)&bias[16 * wp];
        const float4 bB = *(const float4*)&bias[16 * wp + 4];
        const float4 bC = *(const float4*)&bias[16 * wp + 8];
        const float4 bD = *(const float4*)&bias[16 * wp + 12];
        u64 p[8] = { pk2(bA.x,bA.y), pk2(bA.z,bA.w), pk2(bB.x,bB.y), pk2(bB.z,bB.w),
                     pk2(bC.x,bC.y), pk2(bC.z,bC.w), pk2(bD.x,bD.y), pk2(bD.z,bD.w) };
        #pragma unroll
        for (int j = 0; j < 8; j++) { acc[0][j] = p[j]; acc[1][j] = p[j]; }
        if (MODE == 2) { accS[0] = bias[256 + wp]; accS[1] = accS[0]; }
    }

    float* buf0 = sm + OFF_W0;
    float* buf1 = sm + OFF_W1;
    float4 rg[2];
    stage_ld<NCOLS>(Wg, ldw, 0, rg);
    stage_st<NCOLS>(buf0, rg);
    __syncthreads();

    for (int ch = 0; ch < NCH; ch++) {
        const float* cur = (ch & 1) ? buf1 : buf0;
        float* nxt = (ch & 1) ? buf0 : buf1;
        if (ch + 1 < NCH) stage_ld<NCOLS>(Wg, ldw, ch + 1, rg);
        const int kc = ch * 8;
        #pragma unroll
        for (int kk = 0; kk < 8; kk++) {
            float2 hx = *(const float2*)&sHin[(kc + kk) * 64 + 2 * tx];
            u64 h0 = pk2(hx.x, hx.x), h1 = pk2(hx.y, hx.y);
            const float* wr = cur + kk * NCOLS + 16 * wp;
            #pragma unroll
            for (int j4 = 0; j4 < 4; j4++) {
                ulonglong2 w = *(const ulonglong2*)(wr + 4 * j4);
                fma2(acc[0][2*j4],   h0, w.x);
                fma2(acc[0][2*j4+1], h0, w.y);
                fma2(acc[1][2*j4],   h1, w.x);
                fma2(acc[1][2*j4+1], h1, w.y);
            }
            if (MODE == 2) {
                float ws = cur[kk * NCOLS + 256 + wp];
                accS[0] += hx.x * ws;
                accS[1] += hx.y * ws;
            }
        }
        if (ch + 1 < NCH) stage_st<NCOLS>(nxt, rg);
        __syncthreads();
    }

    // epilogue
    #pragma unroll
    for (int ss = 0; ss < 2; ss++) {
        const int s = 2 * tx + ss;
        #pragma unroll
        for (int j = 0; j < 8; j++) {
            float2 p = up2(acc[ss][j]);
            const int c = 16 * wp + 2 * j;
            if (MODE == 0) {
                outp[c * 64 + s]       = ftanh(p.x);
                outp[(c + 1) * 64 + s] = ftanh(p.y);
            } else if (MODE == 1) {
                bool dg = (wp < 2);   // cols 0..31 are diag path (warp-uniform)
                outp[s * LSTRIDE + c]     = dg ? fsplus(p.x) : 0.1f * ftanh(p.x);
                outp[s * LSTRIDE + c + 1] = dg ? fsplus(p.y) : 0.1f * ftanh(p.y);
            } else {
                outp[s * LSTRIDE + 256 + c]     = 0.1f * ftanh(p.x);
                outp[s * LSTRIDE + 256 + c + 1] = 0.1f * ftanh(p.y);
            }
        }
        if (MODE == 2)
            outp[s * LSTRIDE + 512 + wp] = 0.1f * ftanh(accS[ss]);
    }
}

__global__ void __launch_bounds__(NTHREADS, 1) covnet_kernel(
    const float* __restrict__ P_prev,
    const float* __restrict__ W1, const float* __restrict__ b1,
    const float* __restrict__ W2, const float* __restrict__ b2,
    const float* __restrict__ W3, const float* __restrict__ b3,
    const float* __restrict__ Q, float* __restrict__ out)
{
    extern __shared__ float sm[];
    const int tid = threadIdx.x;
    const int tx = tid & 31;
    const int wp = tid >> 5;
    const size_t b0 = (size_t)blockIdx.x * BM;

    // Q -> smem
    for (int i = tid; i < NXD * NXD; i += NTHREADS) sm[OFF_Q + i] = Q[i];

    // gather diagonal (transposed): sXt[d][s] = log(clip(P_prev[s,d,d]))
    for (int i = tid; i < NXD * BM; i += NTHREADS) {
        int d = i >> 6, s = i & 63;
        float v = P_prev[(b0 + (size_t)s) * 1024 + d * 33];
        sm[OFF_X + d * 64 + s] = __logf(fmaxf(v, 1e-6f));
    }
    __syncthreads();

    gemm_f2<32,  256, 0>(sm, W1,        HID,  b1,       sm + OFF_X,  sm + OFF_H1, tx, wp);
    gemm_f2<256, 256, 0>(sm, W2,        HID,  b2,       sm + OFF_H1, sm + OFF_H2, tx, wp);
    gemm_f2<256, 256, 1>(sm, W3,        NOUT, b3,       sm + OFF_H2, sm + OFF_L,  tx, wp);
    gemm_f2<256, 272, 2>(sm, W3 + 256,  NOUT, b3 + 256, sm + OFF_H2, sm + OFF_L,  tx, wp);
    __syncthreads();

    // ================= P = L * L^T + Q =================
    // warp = 4 samples; lane k owns output column k.
    {
        const int k = tx;
        const int s0 = wp * 4;
        const int kbase = 32 + (k * (k - 1)) / 2;
        for (int ss = 0; ss < 4; ss++) {
            const int s = s0 + ss;
            const float* Lr = sm + OFF_L + s * LSTRIDE;
            float Lk[32];
            #pragma unroll
            for (int j = 0; j < 32; j++) {
                float v = 0.f;
                if (j < k)       v = Lr[kbase + j];
                else if (j == k) v = Lr[k];
                Lk[j] = v;
            }
            float* Po = out + (b0 + (size_t)s) * 1024;
            #pragma unroll
            for (int i = 0; i < 32; i++) {
                float a = sm[OFF_Q + i * 32 + k];
                const int ib = 32 + (i * (i - 1)) / 2;
                #pragma unroll
                for (int j = 0; j < i; j++) {
                    float lij = Lr[ib + j];      // warp-uniform broadcast
                    if (j <= k) a += lij * Lk[j];
                }
                float lii = Lr[i];
                if (i <= k) a += lii * Lk[i];
                Po[i * 32 + k] = a;
            }
        }
    }
}

extern "C" void kernel_launch(void* const* d_in, const int* in_sizes, int n_in,
                              void* d_out, int out_size) {
    const float* P_prev = (const float*)d_in[0];
    const float* W1 = (const float*)d_in[1];
    const float* b1 = (const float*)d_in[2];
    const float* W2 = (const float*)d_in[3];
    const float* b2 = (const float*)d_in[4];
    const float* W3 = (const float*)d_in[5];
    const float* b3 = (const float*)d_in[6];
    const float* Q  = (const float*)d_in[7];
    float* out = (float*)d_out;

    const int B = in_sizes[0] / (NXD * NXD);   // 65536
    const int grid = B / BM;                   // 1024

    cudaFuncSetAttribute(covnet_kernel,
                         cudaFuncAttributeMaxDynamicSharedMemorySize,
                         SMEM_FLOATS * sizeof(float));

    covnet_kernel<<<grid, NTHREADS, SMEM_FLOATS * sizeof(float)>>>(
        P_prev, W1, b1, W2, b2, W3, b3, Q, out);
}